// round 1
// baseline (speedup 1.0000x reference)
#include <cuda_runtime.h>
#include <math.h>

// Problem constants
#define BSZ   16
#define SEQ   1024
#define DIM   512
#define NH    8
#define HD    64
#define MTOT  (BSZ*SEQ)          // 16384 rows
#define NEGV  (-4294967295.0f)

// 8 scratch matrices of [16384 x 512] f32 (256 MB, static device allocation)
__device__ float g_buf[8u * MTOT * DIM];

// ---------------------------------------------------------------------------
// GEMM: C[M,512] = A[M,512] @ B  (B is [512,512]; TRANSB -> C=A@B^T)
// Tiles 128x64x16, 256 threads, 8x4 micro-tile per thread.
// ---------------------------------------------------------------------------
template<bool TRANSB, bool BIAS, bool RELU>
__global__ void __launch_bounds__(256) gemm512(const float* __restrict__ A,
                                               const float* __restrict__ B,
                                               const float* __restrict__ bias,
                                               float* __restrict__ C) {
    __shared__ float Ast[16][132];   // A tile transposed: Ast[k][m]
    __shared__ float Bs[16][68];     // Bs[k][n]
    const int tid = threadIdx.x;
    const int tx = tid & 15, ty = tid >> 4;
    const int m0 = blockIdx.y * 128, n0 = blockIdx.x * 64;

    float acc[8][4];
#pragma unroll
    for (int i = 0; i < 8; i++)
#pragma unroll
        for (int j = 0; j < 4; j++) acc[i][j] = 0.f;

    for (int k0 = 0; k0 < 512; k0 += 16) {
        __syncthreads();
        // Load A tile (128x16) -> transpose into Ast
#pragma unroll
        for (int r = 0; r < 2; r++) {
            int f   = tid + r * 256;          // 0..511 (512 float4)
            int row = f >> 2, k4 = f & 3;
            float4 v = *(const float4*)(A + (size_t)(m0 + row) * 512 + k0 + k4 * 4);
            Ast[k4 * 4 + 0][row] = v.x;
            Ast[k4 * 4 + 1][row] = v.y;
            Ast[k4 * 4 + 2][row] = v.z;
            Ast[k4 * 4 + 3][row] = v.w;
        }
        // Load B tile (16x64)
        if (!TRANSB) {
            int kk = tid >> 4, n4 = tid & 15;
            float4 v = *(const float4*)(B + (size_t)(k0 + kk) * 512 + n0 + n4 * 4);
            *(float4*)&Bs[kk][n4 * 4] = v;
        } else {
            int n = tid >> 2, k4 = tid & 3;
            float4 v = *(const float4*)(B + (size_t)(n0 + n) * 512 + k0 + k4 * 4);
            Bs[k4 * 4 + 0][n] = v.x;
            Bs[k4 * 4 + 1][n] = v.y;
            Bs[k4 * 4 + 2][n] = v.z;
            Bs[k4 * 4 + 3][n] = v.w;
        }
        __syncthreads();
#pragma unroll
        for (int kk = 0; kk < 16; kk++) {
            float4 a0 = *(float4*)&Ast[kk][ty * 8];
            float4 a1 = *(float4*)&Ast[kk][ty * 8 + 4];
            float4 bv = *(float4*)&Bs[kk][tx * 4];
            float a[8] = {a0.x, a0.y, a0.z, a0.w, a1.x, a1.y, a1.z, a1.w};
            float bb[4] = {bv.x, bv.y, bv.z, bv.w};
#pragma unroll
            for (int i = 0; i < 8; i++)
#pragma unroll
                for (int j = 0; j < 4; j++) acc[i][j] += a[i] * bb[j];
        }
    }
    // Epilogue
#pragma unroll
    for (int i = 0; i < 8; i++) {
        int row = m0 + ty * 8 + i;
        int col = n0 + tx * 4;
        float4 v;
        v.x = acc[i][0]; v.y = acc[i][1]; v.z = acc[i][2]; v.w = acc[i][3];
        if (BIAS) {
            v.x += bias[col + 0]; v.y += bias[col + 1];
            v.z += bias[col + 2]; v.w += bias[col + 3];
        }
        if (RELU) {
            v.x = fmaxf(v.x, 0.f); v.y = fmaxf(v.y, 0.f);
            v.z = fmaxf(v.z, 0.f); v.w = fmaxf(v.w, 0.f);
        }
        *(float4*)(C + (size_t)row * 512 + col) = v;
    }
}

// ---------------------------------------------------------------------------
// Fused flash attention: one block = 64 query rows of one (b,h).
// Online softmax over key tiles of 64. 256 threads, 4x4 micro-tile.
// smem strides of 68 floats for bank-conflict avoidance + float4 alignment.
// ---------------------------------------------------------------------------
__global__ void __launch_bounds__(256) attn_kernel(const float* __restrict__ Q,
                                                   const float* __restrict__ K,
                                                   const float* __restrict__ V,
                                                   const unsigned char* __restrict__ mask,
                                                   float* __restrict__ O) {
    extern __shared__ float sm[];
    float* Qs = sm;                 // Qs[q][k]   64x68
    float* Kt = sm + 64 * 68;       // Kt[k][c]   64x68 (transposed)
    float* Vs = sm + 2 * 64 * 68;   // Vs[c][d]   64x68
    float* Ps = sm + 3 * 64 * 68;   // Ps[q][c]   64x68

    const int tid = threadIdx.x;
    const int tx = tid & 15, ty = tid >> 4;
    const int q0 = blockIdx.x * 64;
    const int h  = blockIdx.y;
    const int b  = blockIdx.z;
    const float inv_temp = 1.0f / (8.0f + 1e-6f);

    // Load Q tile
#pragma unroll
    for (int r = 0; r < 4; r++) {
        int f = tid + r * 256;          // 0..1023 (1024 float4)
        int row = f >> 4, k4 = f & 15;
        float4 v = *(const float4*)(Q + ((size_t)b * SEQ + q0 + row) * DIM + h * HD + k4 * 4);
        *(float4*)&Qs[row * 68 + k4 * 4] = v;
    }

    float m[4], l[4], o[4][4];
#pragma unroll
    for (int i = 0; i < 4; i++) {
        m[i] = -INFINITY; l[i] = 0.f;
#pragma unroll
        for (int j = 0; j < 4; j++) o[i][j] = 0.f;
    }

    for (int kb = 0; kb < SEQ; kb += 64) {
        __syncthreads();
        // Load K (transposed) and V tiles
#pragma unroll
        for (int r = 0; r < 4; r++) {
            int f = tid + r * 256;
            int row = f >> 4, k4 = f & 15;
            size_t goff = ((size_t)b * SEQ + kb + row) * DIM + h * HD + k4 * 4;
            float4 kv = *(const float4*)(K + goff);
            Kt[(k4 * 4 + 0) * 68 + row] = kv.x;
            Kt[(k4 * 4 + 1) * 68 + row] = kv.y;
            Kt[(k4 * 4 + 2) * 68 + row] = kv.z;
            Kt[(k4 * 4 + 3) * 68 + row] = kv.w;
            float4 vv = *(const float4*)(V + goff);
            *(float4*)&Vs[row * 68 + k4 * 4] = vv;
        }
        __syncthreads();

        // S = Q K^T
        float s[4][4];
#pragma unroll
        for (int i = 0; i < 4; i++)
#pragma unroll
            for (int j = 0; j < 4; j++) s[i][j] = 0.f;
#pragma unroll
        for (int kk = 0; kk < 64; kk++) {
            float4 bv = *(float4*)&Kt[kk * 68 + tx * 4];
            float bb[4] = {bv.x, bv.y, bv.z, bv.w};
#pragma unroll
            for (int i = 0; i < 4; i++) {
                float a = Qs[(ty * 4 + i) * 68 + kk];
#pragma unroll
                for (int j = 0; j < 4; j++) s[i][j] += a * bb[j];
            }
        }
        // scale + mask
        uchar4 mk = *(const uchar4*)(mask + (size_t)b * SEQ + kb + tx * 4);
        unsigned char mkb[4] = {mk.x, mk.y, mk.z, mk.w};
#pragma unroll
        for (int i = 0; i < 4; i++)
#pragma unroll
            for (int j = 0; j < 4; j++) {
                float sv = s[i][j] * inv_temp;
                s[i][j] = mkb[j] ? NEGV : sv;
            }

        // Online softmax
#pragma unroll
        for (int i = 0; i < 4; i++) {
            float tm = fmaxf(fmaxf(s[i][0], s[i][1]), fmaxf(s[i][2], s[i][3]));
#pragma unroll
            for (int off = 8; off; off >>= 1)
                tm = fmaxf(tm, __shfl_xor_sync(0xffffffffu, tm, off));
            float mn = fmaxf(m[i], tm);
            float alpha = __expf(m[i] - mn);
            m[i] = mn;
            float rs = 0.f;
#pragma unroll
            for (int j = 0; j < 4; j++) {
                float p = __expf(s[i][j] - mn);
                s[i][j] = p;
                rs += p;
            }
#pragma unroll
            for (int off = 8; off; off >>= 1)
                rs += __shfl_xor_sync(0xffffffffu, rs, off);
            l[i] = l[i] * alpha + rs;
#pragma unroll
            for (int j = 0; j < 4; j++) o[i][j] *= alpha;
            // store P row fragment
            float4 pv;
            pv.x = s[i][0]; pv.y = s[i][1]; pv.z = s[i][2]; pv.w = s[i][3];
            *(float4*)&Ps[(ty * 4 + i) * 68 + tx * 4] = pv;
        }
        __syncthreads();

        // O += P V
#pragma unroll
        for (int cc = 0; cc < 64; cc++) {
            float4 bv = *(float4*)&Vs[cc * 68 + tx * 4];
            float bb[4] = {bv.x, bv.y, bv.z, bv.w};
#pragma unroll
            for (int i = 0; i < 4; i++) {
                float a = Ps[(ty * 4 + i) * 68 + cc];
#pragma unroll
                for (int j = 0; j < 4; j++) o[i][j] += a * bb[j];
            }
        }
    }

    // Write V_att[b, q, h*64 + d]
#pragma unroll
    for (int i = 0; i < 4; i++) {
        float inv_l = 1.0f / l[i];
        float4 v;
        v.x = o[i][0] * inv_l; v.y = o[i][1] * inv_l;
        v.z = o[i][2] * inv_l; v.w = o[i][3] * inv_l;
        *(float4*)(O + ((size_t)b * SEQ + q0 + ty * 4 + i) * DIM + h * HD + tx * 4) = v;
    }
}

// ---------------------------------------------------------------------------
// Fused residual add + LayerNorm over rows of 512. 256 threads/row.
// out = LN(A + B) * g + beta
// ---------------------------------------------------------------------------
__global__ void __launch_bounds__(256) ln_residual(const float* __restrict__ A,
                                                   const float* __restrict__ Bm,
                                                   const float* __restrict__ g,
                                                   const float* __restrict__ beta,
                                                   float* __restrict__ out) {
    const int row = blockIdx.x;
    const int tid = threadIdx.x;
    const size_t base = (size_t)row * 512;
    float e0 = A[base + tid]       + Bm[base + tid];
    float e1 = A[base + tid + 256] + Bm[base + tid + 256];
    float s  = e0 + e1;
    float s2 = e0 * e0 + e1 * e1;
#pragma unroll
    for (int off = 16; off; off >>= 1) {
        s  += __shfl_xor_sync(0xffffffffu, s, off);
        s2 += __shfl_xor_sync(0xffffffffu, s2, off);
    }
    __shared__ float ws[8], ws2[8];
    const int wid = tid >> 5, lane = tid & 31;
    if (lane == 0) { ws[wid] = s; ws2[wid] = s2; }
    __syncthreads();
    float ts = 0.f, ts2 = 0.f;
#pragma unroll
    for (int w = 0; w < 8; w++) { ts += ws[w]; ts2 += ws2[w]; }
    float mu  = ts * (1.0f / 512.0f);
    float var = ts2 * (1.0f / 512.0f) - mu * mu;
    float rsd = rsqrtf(var + 1e-5f);
    out[base + tid]       = (e0 - mu) * rsd * g[tid]       + beta[tid];
    out[base + tid + 256] = (e1 - mu) * rsd * g[tid + 256] + beta[tid + 256];
}

// ---------------------------------------------------------------------------
extern "C" void kernel_launch(void* const* d_in, const int* in_sizes, int n_in,
                              void* d_out, int out_size) {
    const float* query = (const float*)d_in[0];
    const float* key   = (const float*)d_in[1];
    const float* value = (const float*)d_in[2];
    const unsigned char* mask = (const unsigned char*)d_in[3];
    const float* Wq = (const float*)d_in[4];
    const float* Wk = (const float*)d_in[5];
    const float* Wv = (const float*)d_in[6];
    const float* Wo = (const float*)d_in[7];
    const float* w1 = (const float*)d_in[8];
    const float* b1 = (const float*)d_in[9];
    const float* w2 = (const float*)d_in[10];
    const float* b2 = (const float*)d_in[11];
    const float* w3 = (const float*)d_in[12];
    const float* b3 = (const float*)d_in[13];
    const float* lng = (const float*)d_in[14];
    const float* lnb = (const float*)d_in[15];
    float* out = (float*)d_out;

    float* base = nullptr;
    cudaGetSymbolAddress((void**)&base, g_buf);
    const size_t N = (size_t)MTOT * DIM;
    float* Qb = base;
    float* Kb = base + 1 * N;
    float* Vb = base + 2 * N;
    float* Va = base + 3 * N;
    float* T0 = base + 4 * N;
    float* X1 = base + 5 * N;
    float* H1 = base + 6 * N;
    float* X2 = base + 7 * N;

    dim3 gg(8, 128), gb(256);

    // QKV projections
    gemm512<false, false, false><<<gg, gb>>>(query, Wq, nullptr, Qb);
    gemm512<false, false, false><<<gg, gb>>>(key,   Wk, nullptr, Kb);
    gemm512<false, false, false><<<gg, gb>>>(value, Wv, nullptr, Vb);

    // Fused attention
    const int attn_smem = 4 * 64 * 68 * (int)sizeof(float);  // 69632
    cudaFuncSetAttribute(attn_kernel, cudaFuncAttributeMaxDynamicSharedMemorySize, attn_smem);
    attn_kernel<<<dim3(SEQ / 64, NH, BSZ), 256, attn_smem>>>(Qb, Kb, Vb, mask, Va);

    // Output projection + residual LN
    gemm512<false, false, false><<<gg, gb>>>(Va, Wo, nullptr, T0);
    ln_residual<<<MTOT, 256>>>(query, T0, lng, lnb, X1);

    // FFN
    gemm512<true, true, true ><<<gg, gb>>>(X1, w1, b1, H1);
    gemm512<true, true, false><<<gg, gb>>>(H1, w2, b2, T0);
    ln_residual<<<MTOT, 256>>>(T0, X1, lng, lnb, X2);

    // Final projection
    gemm512<true, true, false><<<gg, gb>>>(X2, w3, b3, out);
}